// round 8
// baseline (speedup 1.0000x reference)
#include <cuda_runtime.h>

// CASSI forward, fully fused, zero-staging kernel.
//
//   y2[b,i,k]    = sum_l x[b,l,i,k-2l] * phi[i,k-2l]   (0 <= k-2l < N)
//   out[b,l,i,j] = phi[i,j] * y2[b,i,2l+j]
//
// Bijection: out[b,l,i,k-2l] = phi[k-2l] * y2[k]. The thread that owns y2[k]
// writes all its outputs directly — same offsets n = k-2l as its loads, same
// coalescing. No y2 smem, no mid-kernel __syncthreads.
//
// 3 streams per thread: k0=t (pred), k1=t+256 (fully unpredicated, loads AND
// stores), k2=t+512 for t<54 (pred). 256 thr/CTA, 4096 CTAs, 8 CTAs/SM.

#define B_      8
#define L_      28
#define M_      512
#define N_      512
#define STRIDE_ 2
#define NOUT_   (N_ + STRIDE_ * (L_ - 1))   // 566
#define TPB     256
#define TAIL_   (NOUT_ - 2 * TPB)           // 54

__global__ __launch_bounds__(TPB) void cassi_fused_kernel(
    const float* __restrict__ x,
    const float* __restrict__ phi,
    float* __restrict__ out)
{
    __shared__ __align__(16) float phi_s[N_];

    const int bm = blockIdx.x;           // (b, i)
    const int b  = bm / M_;
    const int i  = bm % M_;
    const int t  = threadIdx.x;

    // ---- phi row i -> smem (float4) ----
    {
        const float4* p4 = reinterpret_cast<const float4*>(phi + (size_t)i * N_);
        if (t < N_ / 4)
            reinterpret_cast<float4*>(phi_s)[t] = p4[t];
    }
    __syncthreads();

    const size_t band_stride = (size_t)M_ * N_;
    const float* xb = x   + (size_t)b * (L_ * M_ * N_) + (size_t)i * N_;
    float*       ob = out + (size_t)b * (L_ * M_ * N_) + (size_t)i * N_;

    // ---- accumulate: 3 independent scalar load streams (proven best MLP) ----
    float acc0 = 0.f, acc1 = 0.f, acc2 = 0.f;
    {
        const float* xr = xb;
        #pragma unroll
        for (int l = 0; l < L_; ++l) {
            const int n1 = t + TPB - STRIDE_ * l;        // always in [202,511]
            acc1 += __ldcs(xr + n1) * phi_s[n1];

            unsigned n0 = (unsigned)(t - STRIDE_ * l);   // valid iff l <= t/2
            if (n0 < N_) acc0 += __ldcs(xr + n0) * phi_s[n0];

            unsigned n2 = (unsigned)(t + 2 * TPB - STRIDE_ * l); // t<54, l>t/2
            if (t < TAIL_ && n2 < N_) acc2 += __ldcs(xr + n2) * phi_s[n2];

            xr += band_stride;
        }
    }

    // ---- scatter stores: out[b,l,i,n] = phi_s[n] * acc, n = k - 2l ----
    // Same offsets as the loads; consecutive threads -> consecutive columns
    // (coalesced). Stream k1 fully unpredicated.
    {
        float* orow = ob;
        #pragma unroll
        for (int l = 0; l < L_; ++l) {
            const int n1 = t + TPB - STRIDE_ * l;
            __stcs(orow + n1, phi_s[n1] * acc1);

            unsigned n0 = (unsigned)(t - STRIDE_ * l);
            if (n0 < N_) __stcs(orow + n0, phi_s[n0] * acc0);

            unsigned n2 = (unsigned)(t + 2 * TPB - STRIDE_ * l);
            if (t < TAIL_ && n2 < N_) __stcs(orow + n2, phi_s[n2] * acc2);

            orow += band_stride;
        }
    }
}

extern "C" void kernel_launch(void* const* d_in, const int* in_sizes, int n_in,
                              void* d_out, int out_size)
{
    const float* x   = (const float*)d_in[0];
    const float* phi = (const float*)d_in[1];
    float* out       = (float*)d_out;

    cassi_fused_kernel<<<B_ * M_, TPB>>>(x, phi, out);
}

// round 9
// speedup vs baseline: 1.2186x; 1.2186x over previous
#include <cuda_runtime.h>

// CASSI forward, half-row-per-CTA fused kernel.
//
//   y2[b,i,k]    = sum_l x[b,l,i,k-2l] * phi[i,k-2l]   (0 <= k-2l < N)
//   out[b,l,i,j] = phi[i,j] * y2[b,i,2l+j]
//
// R9: halve CTA granularity to cut the end-of-kernel drain loss.
// TPB=128, 8192 CTAs (one per (b,i,half)), 16 CTAs/SM -> 2048 thr/SM.
// Each CTA owns k in [half*284, half*284+284) (second half: width 282).
// 3 scalar accumulation streams per thread (R4's proven MLP shape), then a
// conflict-free float2 epilogue over this CTA's sliding output window.

#define B_      8
#define L_      28
#define M_      512
#define N_      512
#define STRIDE_ 2
#define NOUT_   (N_ + STRIDE_ * (L_ - 1))   // 566
#define TPB     128
#define HALFW_  284                          // words per half (2nd: 282 used)
#define HALF2_  (HALFW_ / 2)                 // 142 float2

__global__ __launch_bounds__(TPB, 16) void cassi_half_kernel(
    const float* __restrict__ x,
    const float* __restrict__ phi,
    float* __restrict__ out)
{
    __shared__ __align__(16) float phi_s[N_];
    __shared__ __align__(16) float y2_s[HALFW_ + 2];

    const int blk  = blockIdx.x;
    const int bm   = blk >> 1;            // (b, i)
    const int half = blk & 1;
    const int b    = bm / M_;
    const int i    = bm % M_;
    const int t    = threadIdx.x;

    // ---- full phi row i -> smem: 128 threads x 1 float4 = 512 floats ----
    {
        const float4* p4 = reinterpret_cast<const float4*>(phi + (size_t)i * N_);
        reinterpret_cast<float4*>(phi_s)[t] = p4[t];
    }
    __syncthreads();

    const size_t band_stride = (size_t)M_ * N_;
    const float* xb = x + (size_t)b * (L_ * M_ * N_) + (size_t)i * N_;

    // ---- accumulate 3 scalar streams: k = base+t, base+128+t, base+256+t ----
    const int base = half * HALFW_;       // 0 or 284
    const int k0 = base + t;
    const int k1 = k0 + TPB;
    const int k2 = k0 + 2 * TPB;
    const bool has2 = (t < HALFW_ - 2 * TPB) && (k2 < NOUT_); // t<28 (h0) / t<26 (h1)

    float a0 = 0.f, a1 = 0.f, a2 = 0.f;
    {
        const float* xr = xb;
        #pragma unroll
        for (int l = 0; l < L_; ++l) {
            unsigned n0 = (unsigned)(k0 - STRIDE_ * l);
            unsigned n1 = (unsigned)(k1 - STRIDE_ * l);
            if (n0 < N_) a0 += __ldcs(xr + n0) * phi_s[n0];
            if (n1 < N_) a1 += __ldcs(xr + n1) * phi_s[n1];
            if (has2) {
                unsigned n2 = (unsigned)(k2 - STRIDE_ * l);
                if (n2 < N_) a2 += __ldcs(xr + n2) * phi_s[n2];
            }
            xr += band_stride;
        }
    }

    y2_s[t]           = a0;               // local word index k - base
    y2_s[t + TPB]     = a1;               // k1 - base <= 255 < 284, k1 < 566 always
    if (has2)
        y2_s[t + 2 * TPB] = a2;
    __syncthreads();

    // ---- epilogue: for each l, this CTA owns output float2 columns
    //      j2 in [j2lo, j2hi):  half0 -> [0, 142-l),  half1 -> [142-l, 256).
    //      y2 float2 local index = l + j2 - half*142  (conflict-free LDS.64).
    float* ob = out + (size_t)b * (L_ * M_ * N_) + (size_t)i * N_;
    const float2* phi2 = reinterpret_cast<const float2*>(phi_s);
    const float2* y22  = reinterpret_cast<const float2*>(y2_s);

    #pragma unroll
    for (int l = 0; l < L_; ++l) {
        const int j2lo = half ? (HALF2_ - l) : 0;
        const int j2hi = half ? (N_ / 2)     : (HALF2_ - l);
        float2* orow = reinterpret_cast<float2*>(ob + (size_t)l * band_stride);

        const int ja = j2lo + t;
        if (ja < j2hi) {
            float2 p = phi2[ja];
            float2 y = y22[l + ja - half * HALF2_];
            float2 r; r.x = p.x * y.x; r.y = p.y * y.y;
            __stcs(orow + ja, r);
        }
        const int jb = j2lo + TPB + t;
        if (jb < j2hi) {
            float2 p = phi2[jb];
            float2 y = y22[l + jb - half * HALF2_];
            float2 r; r.x = p.x * y.x; r.y = p.y * y.y;
            __stcs(orow + jb, r);
        }
    }
}

extern "C" void kernel_launch(void* const* d_in, const int* in_sizes, int n_in,
                              void* d_out, int out_size)
{
    const float* x   = (const float*)d_in[0];
    const float* phi = (const float*)d_in[1];
    float* out       = (float*)d_out;

    cassi_half_kernel<<<2 * B_ * M_, TPB>>>(x, phi, out);
}